// round 9
// baseline (speedup 1.0000x reference)
#include <cuda_runtime.h>
#include <math.h>

// Problem constants
#define BSZ 8
#define HH 256
#define WW 256
#define C1 64
#define NBR 6

// Scratch: weighted neighbor frames (B, 6, H, W) = 12.6 MB
__device__ float g_weighted[BSZ * NBR * HH * WW];

// ---------------------------------------------------------------------------
// Kernel A: fused conv1(2->64,3x3)+ReLU+conv2(64->1,1x1)+sigmoid+gate
// 128 threads as 16x8; 4 px/thread; tile = 64x8.  (unchanged from round 8)
// ---------------------------------------------------------------------------
#define TWA 64
#define THA 8

__global__ __launch_bounds__(128) void branch_kernel(
    const float* __restrict__ x,
    const float* __restrict__ W1,
    const float* __restrict__ b1,
    const float* __restrict__ W2,
    const float* __restrict__ b2)
{
    __shared__ float sB[THA + 2][TWA + 4];   // 10 x 68 (272B rows, 16B-aligned)
    __shared__ float sC[THA + 2][TWA + 4];
    // Per-channel packed weights: [0..8]=wb, [9..17]=wc, [18]=b1, [19]=w2, pad->24
    __shared__ float sWp[C1][24];

    const int bz  = blockIdx.z;
    const int b   = bz / NBR;
    const int n   = bz % NBR;
    const int ty0 = blockIdx.y * THA;
    const int tx0 = blockIdx.x * TWA;
    const int tid = threadIdx.x;
    const int lane = tid & 31;
    const int wrp  = tid >> 5;

    const int checkCh = (n < 3) ? n : (n + 1);
    const int bi = (n < 3) ? 0 : 1;   // pair channel that holds base

    const float* __restrict__ base = x + (size_t)(b * 7 + 3) * (HH * WW);
    const float* __restrict__ chk  = x + (size_t)(b * 7 + checkCh) * (HH * WW);

    // Stage packed weights
    for (int i = tid; i < C1 * 9; i += 128) {
        int c = i / 9, k = i - c * 9;
        sWp[c][k]     = W1[((n * C1 + c) * 2 + bi) * 9 + k];
        sWp[c][9 + k] = W1[((n * C1 + c) * 2 + (1 - bi)) * 9 + k];
    }
    if (tid < C1) {
        sWp[tid][18] = b1[n * C1 + tid];
        sWp[tid][19] = W2[n * C1 + tid];
    }

    // Stage input tiles (warp-stripe: warp -> rows, lane -> cols)
    const bool interior = (ty0 > 0) && (ty0 + THA < HH) && (tx0 > 0) && (tx0 + TWA < WW);
    if (interior) {
        for (int r = wrp; r < THA + 2; r += 4) {
            const float* pb = base + (ty0 + r - 1) * WW + (tx0 - 1);
            const float* pc = chk  + (ty0 + r - 1) * WW + (tx0 - 1);
            sB[r][lane]      = pb[lane];
            sB[r][32 + lane] = pb[32 + lane];
            sC[r][lane]      = pc[lane];
            sC[r][32 + lane] = pc[32 + lane];
            if (lane < 2) {
                sB[r][64 + lane] = pb[64 + lane];
                sC[r][64 + lane] = pc[64 + lane];
            }
        }
    } else {
        for (int r = wrp; r < THA + 2; r += 4) {
            const int gy = ty0 + r - 1;
            const bool okY = (gy >= 0) && (gy < HH);
            const float* pb = base + gy * WW;
            const float* pc = chk  + gy * WW;
#pragma unroll
            for (int s = 0; s < 3; s++) {
                int cc = lane + 32 * s;
                if (cc < TWA + 2) {
                    int gx = tx0 + cc - 1;
                    bool ok = okY && (gx >= 0) && (gx < WW);
                    sB[r][cc] = ok ? pb[gx] : 0.0f;
                    sC[r][cc] = ok ? pc[gx] : 0.0f;
                }
            }
        }
    }
    __syncthreads();

    const int lx = tid & 15;
    const int ly = tid >> 4;
    const int px = lx * 4;

    // Register taps: 3 rows x 6 cols per input (4 px + 2 halo)
    float tB[3][6], tC[3][6];
#pragma unroll
    for (int r = 0; r < 3; r++) {
        const float* rb = &sB[ly + r][px];
        const float* rc = &sC[ly + r][px];
        float4 b4 = *reinterpret_cast<const float4*>(rb);
        float2 b2v = *reinterpret_cast<const float2*>(rb + 4);
        float4 c4 = *reinterpret_cast<const float4*>(rc);
        float2 c2 = *reinterpret_cast<const float2*>(rc + 4);
        tB[r][0]=b4.x; tB[r][1]=b4.y; tB[r][2]=b4.z; tB[r][3]=b4.w;
        tB[r][4]=b2v.x; tB[r][5]=b2v.y;
        tC[r][0]=c4.x; tC[r][1]=c4.y; tC[r][2]=c4.z; tC[r][3]=c4.w;
        tC[r][4]=c2.x; tC[r][5]=c2.y;
    }

    float s0 = 0.f, s1 = 0.f, s2 = 0.f, s3 = 0.f;

#define BSTEP(U, V, R, K)                                      \
    a0 = fmaf(U, tB[R][K],     fmaf(V, tC[R][K],     a0));     \
    a1 = fmaf(U, tB[R][K + 1], fmaf(V, tC[R][K + 1], a1));     \
    a2 = fmaf(U, tB[R][K + 2], fmaf(V, tC[R][K + 2], a2));     \
    a3 = fmaf(U, tB[R][K + 3], fmaf(V, tC[R][K + 3], a3));

#pragma unroll 2
    for (int c = 0; c < C1; c++) {
        const float4 wA = *reinterpret_cast<const float4*>(&sWp[c][0]);
        const float4 wB = *reinterpret_cast<const float4*>(&sWp[c][4]);
        const float4 wC = *reinterpret_cast<const float4*>(&sWp[c][8]);
        const float4 wD = *reinterpret_cast<const float4*>(&sWp[c][12]);
        const float4 wE = *reinterpret_cast<const float4*>(&sWp[c][16]);
        // wb[0..8] = wA.x wA.y wA.z wA.w wB.x wB.y wB.z wB.w wC.x
        // wc[0..8] = wC.y wC.z wC.w wD.x wD.y wD.z wD.w wE.x wE.y
        // bias = wE.z, w2 = wE.w

        float a0 = fmaf(wA.x, tB[0][0], fmaf(wC.y, tC[0][0], wE.z));
        float a1 = fmaf(wA.x, tB[0][1], fmaf(wC.y, tC[0][1], wE.z));
        float a2 = fmaf(wA.x, tB[0][2], fmaf(wC.y, tC[0][2], wE.z));
        float a3 = fmaf(wA.x, tB[0][3], fmaf(wC.y, tC[0][3], wE.z));

        BSTEP(wA.y, wC.z, 0, 1)
        BSTEP(wA.z, wC.w, 0, 2)
        BSTEP(wA.w, wD.x, 1, 0)
        BSTEP(wB.x, wD.y, 1, 1)
        BSTEP(wB.y, wD.z, 1, 2)
        BSTEP(wB.z, wD.w, 2, 0)
        BSTEP(wB.w, wE.x, 2, 1)
        BSTEP(wC.x, wE.y, 2, 2)

        s0 = fmaf(wE.w, fmaxf(a0, 0.f), s0);
        s1 = fmaf(wE.w, fmaxf(a1, 0.f), s1);
        s2 = fmaf(wE.w, fmaxf(a2, 0.f), s2);
        s3 = fmaf(wE.w, fmaxf(a3, 0.f), s3);
    }
#undef BSTEP

    const float bb2 = b2[n];
    const float g0 = 1.f / (1.f + __expf(-(s0 + bb2)));
    const float g1 = 1.f / (1.f + __expf(-(s1 + bb2)));
    const float g2 = 1.f / (1.f + __expf(-(s2 + bb2)));
    const float g3 = 1.f / (1.f + __expf(-(s3 + bb2)));

    const int gy = ty0 + ly;
    float* o = g_weighted + ((size_t)(b * NBR + n) * HH + gy) * WW + tx0 + px;
    float4 w4;
    w4.x = g0 * tC[1][1];
    w4.y = g1 * tC[1][2];
    w4.z = g2 * tC[1][3];
    w4.w = g3 * tC[1][4];
    *reinterpret_cast<float4*>(o) = w4;
}

// ---------------------------------------------------------------------------
// Kernel B: final 7->7 3x3 conv. 128 threads (16x8), 4 px/thread, 64x8 tile.
// Grid 1024 -> ~1 wave at ~7 blocks/SM; high FMA density per LDS.
// ---------------------------------------------------------------------------
#define TWB 64
#define THB 8

__global__ __launch_bounds__(128) void merge_kernel(
    const float* __restrict__ x,
    const float* __restrict__ Wm,
    const float* __restrict__ bm,
    float* __restrict__ out)
{
    __shared__ float sIn[7][THB + 2][TWB + 4];   // 7 x 10 x 68 (19 KB)
    __shared__ float sW[7][7][12];               // 9 weights padded to 12
    __shared__ float sbm[7];

    const int b   = blockIdx.z;
    const int ty0 = blockIdx.y * THB;
    const int tx0 = blockIdx.x * TWB;
    const int tid = threadIdx.x;
    const int lane = tid & 31;
    const int wrp  = tid >> 5;

    for (int i = tid; i < 7 * 7 * 9; i += 128) {
        int pair = i / 9, k = i - pair * 9;
        sW[pair / 7][pair % 7][k] = Wm[i];
    }
    if (tid < 7) sbm[tid] = bm[tid];

    // Staging: p enumerates (ch, row) pairs; lane covers 66 columns (coalesced)
    const bool interior = (ty0 > 0) && (ty0 + THB < HH) && (tx0 > 0) && (tx0 + TWB < WW);
    const float* __restrict__ xc = x + (size_t)(b * 7 + 3) * (HH * WW);
    const float* __restrict__ gw = g_weighted + (size_t)(b * NBR) * (HH * WW);

    if (interior) {
#pragma unroll 1
        for (int p = wrp; p < 70; p += 4) {
            const int ch = p / 10;
            const int r  = p - ch * 10;
            const float* src;
            if (ch == 3) src = xc;
            else {
                int m = (ch < 3) ? ch : (ch - 1);
                src = gw + (size_t)m * (HH * WW);
            }
            const float* row = src + (ty0 + r - 1) * WW + (tx0 - 1);
            sIn[ch][r][lane]      = row[lane];
            sIn[ch][r][32 + lane] = row[32 + lane];
            if (lane < 2) sIn[ch][r][64 + lane] = row[64 + lane];
        }
    } else {
#pragma unroll 1
        for (int p = wrp; p < 70; p += 4) {
            const int ch = p / 10;
            const int r  = p - ch * 10;
            const float* src;
            if (ch == 3) src = xc;
            else {
                int m = (ch < 3) ? ch : (ch - 1);
                src = gw + (size_t)m * (HH * WW);
            }
            const int gy = ty0 + r - 1;
            const bool okY = (gy >= 0) && (gy < HH);
#pragma unroll
            for (int s = 0; s < 3; s++) {
                const int cc = lane + 32 * s;
                if (cc < TWB + 2) {
                    const int gx = tx0 + cc - 1;
                    float v = 0.f;
                    if (okY && gx >= 0 && gx < WW) v = src[gy * WW + gx];
                    sIn[ch][r][cc] = v;
                }
            }
        }
    }
    __syncthreads();

    const int lx = tid & 15;
    const int ly = tid >> 4;
    const int px = lx * 4;

    float acc[7][4];
#pragma unroll
    for (int co = 0; co < 7; co++) {
        const float bv = sbm[co];
        acc[co][0] = bv; acc[co][1] = bv; acc[co][2] = bv; acc[co][3] = bv;
    }

#pragma unroll
    for (int ci = 0; ci < 7; ci++) {
        // Taps: 3 rows x 6 cols (4 px + 2 halo)
        float t[3][6];
#pragma unroll
        for (int r = 0; r < 3; r++) {
            const float* rp = &sIn[ci][ly + r][px];
            float4 v4 = *reinterpret_cast<const float4*>(rp);
            float2 v2 = *reinterpret_cast<const float2*>(rp + 4);
            t[r][0] = v4.x; t[r][1] = v4.y; t[r][2] = v4.z;
            t[r][3] = v4.w; t[r][4] = v2.x; t[r][5] = v2.y;
        }

#pragma unroll
        for (int co = 0; co < 7; co++) {
            const float4 wA = *reinterpret_cast<const float4*>(&sW[co][ci][0]);
            const float4 wB = *reinterpret_cast<const float4*>(&sW[co][ci][4]);
            const float  w8 = sW[co][ci][8];
            // row0: wA.x wA.y wA.z ; row1: wA.w wB.x wB.y ; row2: wB.z wB.w w8
            float p0 = acc[co][0], p1 = acc[co][1], p2 = acc[co][2], p3 = acc[co][3];
            p0 = fmaf(wA.x, t[0][0], p0); p1 = fmaf(wA.x, t[0][1], p1);
            p2 = fmaf(wA.x, t[0][2], p2); p3 = fmaf(wA.x, t[0][3], p3);
            p0 = fmaf(wA.y, t[0][1], p0); p1 = fmaf(wA.y, t[0][2], p1);
            p2 = fmaf(wA.y, t[0][3], p2); p3 = fmaf(wA.y, t[0][4], p3);
            p0 = fmaf(wA.z, t[0][2], p0); p1 = fmaf(wA.z, t[0][3], p1);
            p2 = fmaf(wA.z, t[0][4], p2); p3 = fmaf(wA.z, t[0][5], p3);
            p0 = fmaf(wA.w, t[1][0], p0); p1 = fmaf(wA.w, t[1][1], p1);
            p2 = fmaf(wA.w, t[1][2], p2); p3 = fmaf(wA.w, t[1][3], p3);
            p0 = fmaf(wB.x, t[1][1], p0); p1 = fmaf(wB.x, t[1][2], p1);
            p2 = fmaf(wB.x, t[1][3], p2); p3 = fmaf(wB.x, t[1][4], p3);
            p0 = fmaf(wB.y, t[1][2], p0); p1 = fmaf(wB.y, t[1][3], p1);
            p2 = fmaf(wB.y, t[1][4], p2); p3 = fmaf(wB.y, t[1][5], p3);
            p0 = fmaf(wB.z, t[2][0], p0); p1 = fmaf(wB.z, t[2][1], p1);
            p2 = fmaf(wB.z, t[2][2], p2); p3 = fmaf(wB.z, t[2][3], p3);
            p0 = fmaf(wB.w, t[2][1], p0); p1 = fmaf(wB.w, t[2][2], p1);
            p2 = fmaf(wB.w, t[2][3], p2); p3 = fmaf(wB.w, t[2][4], p3);
            p0 = fmaf(w8,   t[2][2], p0); p1 = fmaf(w8,   t[2][3], p1);
            p2 = fmaf(w8,   t[2][4], p2); p3 = fmaf(w8,   t[2][5], p3);
            acc[co][0] = p0; acc[co][1] = p1; acc[co][2] = p2; acc[co][3] = p3;
        }
    }

    const int gy = ty0 + ly;
#pragma unroll
    for (int co = 0; co < 7; co++) {
        float* o = out + ((size_t)(b * 7 + co) * HH + gy) * WW + tx0 + px;
        float4 v4;
        v4.x = acc[co][0]; v4.y = acc[co][1]; v4.z = acc[co][2]; v4.w = acc[co][3];
        *reinterpret_cast<float4*>(o) = v4;
    }
}

// ---------------------------------------------------------------------------
extern "C" void kernel_launch(void* const* d_in, const int* in_sizes, int n_in,
                              void* d_out, int out_size)
{
    const float* x  = (const float*)d_in[0];   // (8, 7, 256, 256)
    const float* W1 = (const float*)d_in[1];   // (6, 64, 2, 3, 3)
    const float* b1 = (const float*)d_in[2];   // (6, 64)
    const float* W2 = (const float*)d_in[3];   // (6, 1, 64, 1, 1)
    const float* b2 = (const float*)d_in[4];   // (6, 1)
    const float* Wm = (const float*)d_in[5];   // (7, 7, 3, 3)
    const float* bm = (const float*)d_in[6];   // (7,)

    dim3 grid1(WW / TWA, HH / THA, BSZ * NBR);   // 4 x 32 x 48 = 6144
    branch_kernel<<<grid1, 128>>>(x, W1, b1, W2, b2);

    dim3 grid2(WW / TWB, HH / THB, BSZ);         // 4 x 32 x 8 = 1024
    merge_kernel<<<grid2, 128>>>(x, Wm, bm, (float*)d_out);
}